// round 1
// baseline (speedup 1.0000x reference)
#include <cuda_runtime.h>
#include <cstdint>

// One warp per row of 128 floats (32 x float4).
// Lane 0 loads the first float4 (cols 0..3), broadcasts hunger/social/wealth.
// Warp-uniform branch:
//   any_rule  -> write one-hot row (zeros except cols 0..2), NO further input reads
//   !any_rule -> all lanes load their float4 and copy it out
__global__ __launch_bounds__(256, 8)
void symbolic_rules_kernel(const float4* __restrict__ in,
                           float4* __restrict__ out,
                           int nrows) {
    const int warp_global = (blockIdx.x * blockDim.x + threadIdx.x) >> 5;
    const int lane = threadIdx.x & 31;
    if (warp_global >= nrows) return;

    const long long base = (long long)warp_global * 32;

    float4 v;
    if (lane == 0) v = in[base];

    const float h = __shfl_sync(0xffffffffu, v.x, 0);
    const float s = __shfl_sync(0xffffffffu, v.y, 0);
    const float w = __shfl_sync(0xffffffffu, v.z, 0);

    const bool c1 = h > 0.8f;
    const bool c2 = (!c1) && (s < 0.3f);
    const bool c3 = (!c1) && (!c2) && (w < 0.2f);
    const bool any_rule = c1 || c2 || c3;

    if (any_rule) {
        float4 o = make_float4(0.f, 0.f, 0.f, 0.f);
        if (lane == 0) {
            o.x = c1 ? 1.f : 0.f;
            o.y = c2 ? 1.f : 0.f;
            o.z = c3 ? 1.f : 0.f;
        }
        out[base + lane] = o;
    } else {
        if (lane != 0) v = in[base + lane];
        out[base + lane] = v;
    }
}

extern "C" void kernel_launch(void* const* d_in, const int* in_sizes, int n_in,
                              void* d_out, int out_size) {
    const float4* in = (const float4*)d_in[0];
    float4* out = (float4*)d_out;
    const int nrows = in_sizes[0] / 128;   // 2,000,000

    const int threads = 256;               // 8 warps = 8 rows per block
    const int rows_per_block = threads / 32;
    const int blocks = (nrows + rows_per_block - 1) / rows_per_block;

    symbolic_rules_kernel<<<blocks, threads>>>(in, out, nrows);
}

// round 2
// speedup vs baseline: 1.2199x; 1.2199x over previous
#include <cuda_runtime.h>
#include <cstdint>

// 8 rows per warp. Lanes 0..7 each load the head float4 of one row up front
// (8 independent LDGs in flight), then the warp loops over the 8 rows,
// broadcasting that row's (hunger, social, wealth) via shfl.
// Per row (warp-uniform branch):
//   any_rule  -> write one-hot row, NO further input reads
//   !any_rule -> all 32 lanes load their float4 and copy it out
static constexpr int ROWS_PER_WARP = 8;

__global__ __launch_bounds__(256)
void symbolic_rules_kernel(const float4* __restrict__ in,
                           float4* __restrict__ out,
                           int nrows) {
    const int warp_global = (blockIdx.x * blockDim.x + threadIdx.x) >> 5;
    const int lane = threadIdx.x & 31;

    const long long row0 = (long long)warp_global * ROWS_PER_WARP;
    if (row0 >= nrows) return;

    // Batched predicate loads: lane i (i<8) fetches head of row row0+i.
    float4 head = make_float4(0.f, 0.f, 0.f, 0.f);
    if (lane < ROWS_PER_WARP && (row0 + lane) < nrows) {
        head = __ldcs(&in[(row0 + lane) * 32]);
    }

    #pragma unroll
    for (int i = 0; i < ROWS_PER_WARP; i++) {
        const long long row = row0 + i;
        if (row >= nrows) break;

        const float h = __shfl_sync(0xffffffffu, head.x, i);
        const float s = __shfl_sync(0xffffffffu, head.y, i);
        const float w = __shfl_sync(0xffffffffu, head.z, i);

        const bool c1 = h > 0.8f;
        const bool c2 = (!c1) && (s < 0.3f);
        const bool c3 = (!c1) && (!c2) && (w < 0.2f);
        const bool any_rule = c1 || c2 || c3;

        const long long base = row * 32;

        if (any_rule) {
            float4 o = make_float4(0.f, 0.f, 0.f, 0.f);
            if (lane == 0) {
                o.x = c1 ? 1.f : 0.f;
                o.y = c2 ? 1.f : 0.f;
                o.z = c3 ? 1.f : 0.f;
            }
            out[base + lane] = o;
        } else {
            float4 v = __ldcs(&in[base + lane]);
            out[base + lane] = v;
        }
    }
}

extern "C" void kernel_launch(void* const* d_in, const int* in_sizes, int n_in,
                              void* d_out, int out_size) {
    const float4* in = (const float4*)d_in[0];
    float4* out = (float4*)d_out;
    const int nrows = in_sizes[0] / 128;   // 2,000,000

    const int threads = 256;                               // 8 warps/block
    const int rows_per_block = (threads / 32) * ROWS_PER_WARP;  // 64 rows
    const int blocks = (nrows + rows_per_block - 1) / rows_per_block;

    symbolic_rules_kernel<<<blocks, threads>>>(in, out, nrows);
}